// round 9
// baseline (speedup 1.0000x reference)
#include <cuda_runtime.h>
#include <cuda_bf16.h>
#include <cstdint>
#include <cstddef>

static constexpr int BATCH  = 256;
static constexpr int EDIM   = 512;
static constexpr int NNODES = 16383;
static constexpr int NPAD   = 16384;
static constexpr int VLEAF  = 16384;
static constexpr int TILE_N = 128;
static constexpr int KC     = 64;            // K chunk (elements)
static constexpr int NCHUNK = EDIM / KC;     // 8
static constexpr int NTILES = NPAD / TILE_N; // 128
static constexpr int SROW   = 72;            // padded smem row stride (bf16 elts)

static __device__ float g_delta[(size_t)BATCH * NPAD];

#define DEVINL __device__ __forceinline__

DEVINL uint32_t smem_u32(const void* p) {
    uint32_t a;
    asm("{ .reg .u64 t; cvta.to.shared.u64 t, %1; cvt.u32.u64 %0, t; }" : "=r"(a) : "l"(p));
    return a;
}

#define STS32(a, v) asm volatile("st.shared.b32 [%0], %1;" :: "r"(a), "r"(v) : "memory")
#define STS64(a, v) asm volatile("st.shared.b64 [%0], %1;" :: "r"(a), "l"(v) : "memory")

DEVINL void ldsm_x4(uint32_t* r, uint32_t addr) {
    asm volatile("ldmatrix.sync.aligned.m8n8.x4.shared.b16 {%0,%1,%2,%3}, [%4];"
                 : "=r"(r[0]), "=r"(r[1]), "=r"(r[2]), "=r"(r[3]) : "r"(addr));
}

DEVINL void mma16816(float* c, const uint32_t* a, uint32_t b0, uint32_t b1) {
    asm volatile(
        "mma.sync.aligned.m16n8k16.row.col.f32.bf16.bf16.f32 "
        "{%0,%1,%2,%3}, {%4,%5,%6,%7}, {%8,%9}, {%0,%1,%2,%3};"
        : "+f"(c[0]), "+f"(c[1]), "+f"(c[2]), "+f"(c[3])
        : "r"(a[0]), "r"(a[1]), "r"(a[2]), "r"(a[3]), "r"(b0), "r"(b1));
}

DEVINL uint32_t pack_bf16(float lo, float hi) {   // low half = lo, high = hi
    uint32_t r;
    asm("cvt.rn.bf16x2.f32 %0, %1, %2;" : "=r"(r) : "f"(hi), "f"(lo));
    return r;
}
DEVINL float bf16_rt(float a) { return __bfloat162float(__float2bfloat16(a)); }
DEVINL uint64_t pack2(uint32_t lo, uint32_t hi) { return (uint64_t)lo | ((uint64_t)hi << 32); }

// accurate 2-way softmax from logit diff (no 1-p cancellation)
DEVINL void sig2(float t, float& p0, float& p1) {
    t = fminf(fmaxf(t, -60.f), 60.f);
    float e   = __expf(-t);
    float inv = __fdividef(1.f, 1.f + e);
    p1 = inv;
    p0 = e * inv;
}

// SMEM: bias [0,512); stages @1024, each: Ahi(36864) Alo(36864) Whi(18432) Wlo(18432)
static constexpr uint32_t OFF_BIAS  = 0;
static constexpr uint32_t OFF_STAGE = 1024;
static constexpr uint32_t SO_AHI = 0;
static constexpr uint32_t SO_ALO = 36864;
static constexpr uint32_t SO_WHI = 73728;
static constexpr uint32_t SO_WLO = 92160;
static constexpr uint32_t STAGE_BYTES = 110592;
static constexpr uint32_t GEMM_SMEM = OFF_STAGE + 2 * STAGE_BYTES;  // 222208
static constexpr uint32_t TREE_SMEM = 2 * 8192 * 4;                  // 65536

extern __shared__ char dyn_smem[];

__global__ void __launch_bounds__(256, 1)
hsm_gemm(const float* __restrict__ x, const float* __restrict__ W,
         const float* __restrict__ bias) {
    const uint32_t sb = smem_u32(dyn_smem);
    const int tid = threadIdx.x, wid = tid >> 5, lid = tid & 31;
    const int n0 = blockIdx.x * TILE_N;
    const int mw = wid & 3;   // M warp tile (4 x 64 = 256)
    const int nw = wid >> 2;  // N warp tile (2 x 64 = 128)

    float* sBias = (float*)(dyn_smem + OFF_BIAS);
    if (tid < 128) {
        const int n = n0 + tid;
        sBias[tid] = (n < NNODES) ? (__ldg(bias + 2 * n + 1) - __ldg(bias + 2 * n)) : 0.f;
    }

    // fp32 accumulators: 4 m16 tiles x 8 n8 tiles x 4 regs
    float acc[4][8][4];
    #pragma unroll
    for (int i = 0; i < 4; i++)
        #pragma unroll
        for (int j = 0; j < 8; j++)
            #pragma unroll
            for (int k = 0; k < 4; k++) acc[i][j][k] = 0.f;

    // ---- copy one K chunk into stage (c&1): f32 -> diff -> bf16 hi/lo ----
    auto copy_chunk = [&](int c) {
        const uint32_t st = sb + OFF_STAGE + (uint32_t)(c & 1) * STAGE_BYTES;
        const int k0 = c * KC;
        // W: 128 node rows; warp covers rows [wid*16, wid*16+16); lane = 1 float4 (2 e's)
        #pragma unroll
        for (int it = 0; it < 16; ++it) {
            const int row = wid * 16 + it;
            const int node = n0 + row;
            float d0 = 0.f, d1 = 0.f;
            if (node < NNODES) {
                const float4 q =
                    __ldg((const float4*)(W + (size_t)node * 1024 + k0 * 2) + lid);
                d0 = q.y - q.x;   // e = k0 + 2*lid
                d1 = q.w - q.z;   // e + 1
            }
            const uint32_t hv = pack_bf16(d0, d1);
            const uint32_t lv = pack_bf16(d0 - bf16_rt(d0), d1 - bf16_rt(d1));
            const uint32_t off = (uint32_t)(row * SROW + 2 * lid) * 2;
            STS32(st + SO_WHI + off, hv);
            STS32(st + SO_WLO + off, lv);
        }
        // A (x): 256 rows x 64 floats; 16 threads per row, 1 float4 each
        #pragma unroll
        for (int it = 0; it < 16; ++it) {
            const int idx = it * 256 + tid;
            const int row = idx >> 4, f = idx & 15;
            const float4 q = __ldg((const float4*)(x + (size_t)row * EDIM + k0) + f);
            const uint32_t h01 = pack_bf16(q.x, q.y);
            const uint32_t h23 = pack_bf16(q.z, q.w);
            const uint32_t l01 = pack_bf16(q.x - bf16_rt(q.x), q.y - bf16_rt(q.y));
            const uint32_t l23 = pack_bf16(q.z - bf16_rt(q.z), q.w - bf16_rt(q.w));
            const uint32_t off = (uint32_t)(row * (SROW * 2) + f * 8);
            STS64(st + SO_AHI + off, pack2(h01, h23));
            STS64(st + SO_ALO + off, pack2(l01, l23));
        }
    };

    // ---- MMA one chunk: 4 k16-steps x 3 hi/lo passes x (4x8 tile grid) ----
    auto mma_chunk = [&](int c) {
        const uint32_t st = sb + OFF_STAGE + (uint32_t)(c & 1) * STAGE_BYTES;
        const int arow = mw * 64 + (lid & 15);            // A ldmatrix row
        const int brow = nw * 64 + (lid & 7) + ((lid & 16) ? 8 : 0);
        #pragma unroll
        for (int ks = 0; ks < 4; ks++) {
            const int kA = ks * 16 + ((lid & 16) ? 8 : 0);
            const int kB = ks * 16 + ((lid & 8) ? 8 : 0);
            #pragma unroll
            for (int pass = 0; pass < 3; pass++) {
                const uint32_t Ab = st + (pass == 2 ? SO_ALO : SO_AHI);
                const uint32_t Bb = st + (pass == 1 ? SO_WLO : SO_WHI);
                uint32_t af[4][4], bf[4][4];
                #pragma unroll
                for (int mt = 0; mt < 4; mt++)
                    ldsm_x4(af[mt], Ab + (uint32_t)((arow + mt * 16) * SROW + kA) * 2);
                #pragma unroll
                for (int j = 0; j < 4; j++)
                    ldsm_x4(bf[j], Bb + (uint32_t)((brow + j * 16) * SROW + kB) * 2);
                #pragma unroll
                for (int mt = 0; mt < 4; mt++)
                    #pragma unroll
                    for (int j = 0; j < 4; j++) {
                        mma16816(acc[mt][2 * j],     af[mt], bf[j][0], bf[j][1]);
                        mma16816(acc[mt][2 * j + 1], af[mt], bf[j][2], bf[j][3]);
                    }
            }
        }
    };

    copy_chunk(0);
    __syncthreads();
    for (int c = 0; c < NCHUNK; c++) {
        if (c + 1 < NCHUNK) copy_chunk(c + 1);   // writes other stage
        mma_chunk(c);
        __syncthreads();
    }

    // ---- epilogue: + bias diff, store delta (32B sectors fully used) ----
    #pragma unroll
    for (int mt = 0; mt < 4; mt++) {
        const int r0 = mw * 64 + mt * 16 + (lid >> 2);
        #pragma unroll
        for (int nt = 0; nt < 8; nt++) {
            const int cl = nw * 64 + nt * 8 + 2 * (lid & 3);
            const float b0 = sBias[cl], b1 = sBias[cl + 1];
            float2* p0 = (float2*)(g_delta + (size_t)r0 * NPAD + n0 + cl);
            float2* p1 = (float2*)(g_delta + (size_t)(r0 + 8) * NPAD + n0 + cl);
            *p0 = make_float2(acc[mt][nt][0] + b0, acc[mt][nt][1] + b1);
            *p1 = make_float2(acc[mt][nt][2] + b0, acc[mt][nt][3] + b1);
        }
    }
}

// one block per batch row: level-wise cumulative product down the heap
__global__ void __launch_bounds__(512, 1)
hsm_tree(float* __restrict__ out) {
    float* bufA = (float*)dyn_smem;
    float* bufB = bufA + 8192;
    const int b = blockIdx.x, tid = threadIdx.x;
    const float* dr = g_delta + (size_t)b * NPAD;

    if (tid == 0) {
        float p0, p1;
        sig2(dr[0], p0, p1);
        bufA[0] = p0; bufA[1] = p1;
    }
    __syncthreads();

    float* cur = bufA;
    float* nxt = bufB;
    for (int d = 1; d <= 12; d++) {
        const int sz = 1 << d, base = sz - 1;
        for (int i = tid; i < sz; i += 512) {
            float p0, p1;
            sig2(dr[base + i], p0, p1);
            const float cp = cur[i];
            nxt[2 * i] = cp * p0;
            nxt[2 * i + 1] = cp * p1;
        }
        __syncthreads();
        float* t = cur; cur = nxt; nxt = t;
    }
    float2* out2 = (float2*)(out + (size_t)b * VLEAF);
    for (int i = tid; i < 8192; i += 512) {
        float p0, p1;
        sig2(dr[8191 + i], p0, p1);
        const float cp = cur[i];
        out2[i] = make_float2(cp * p0, cp * p1);
    }
}

extern "C" void kernel_launch(void* const* d_in, const int* in_sizes, int n_in,
                              void* d_out, int out_size) {
    (void)in_sizes; (void)n_in; (void)out_size;
    const float* x    = (const float*)d_in[0];
    const float* W    = (const float*)d_in[1];
    const float* bias = (const float*)d_in[2];
    float* out = (float*)d_out;

    cudaFuncSetAttribute(hsm_gemm, cudaFuncAttributeMaxDynamicSharedMemorySize, GEMM_SMEM);
    cudaFuncSetAttribute(hsm_tree, cudaFuncAttributeMaxDynamicSharedMemorySize, TREE_SMEM);

    hsm_gemm<<<NTILES, 256, GEMM_SMEM>>>(x, W, bias);
    hsm_tree<<<BATCH, 512, TREE_SMEM>>>(out);
}

// round 13
// speedup vs baseline: 1.0005x; 1.0005x over previous
#include <cuda_runtime.h>
#include <cuda_bf16.h>
#include <cstdint>
#include <cstddef>

static constexpr int BATCH  = 256;
static constexpr int EDIM   = 512;
static constexpr int NNODES = 16383;
static constexpr int NPAD   = 16384;
static constexpr int VLEAF  = 16384;
static constexpr int TILE_N = 128;
static constexpr int KC     = 64;            // K chunk (elements)
static constexpr int NCHUNK = EDIM / KC;     // 8
static constexpr int NTILES = NPAD / TILE_N; // 128
static constexpr int SROW   = 72;            // padded smem row stride (bf16 elts)

static __device__ float g_delta[(size_t)BATCH * NPAD];

#define DEVINL __device__ __forceinline__

DEVINL uint32_t smem_u32(const void* p) {
    uint32_t a;
    asm("{ .reg .u64 t; cvta.to.shared.u64 t, %1; cvt.u32.u64 %0, t; }" : "=r"(a) : "l"(p));
    return a;
}

#define STS32(a, v) asm volatile("st.shared.b32 [%0], %1;" :: "r"(a), "r"(v) : "memory")
#define STS64(a, v) asm volatile("st.shared.b64 [%0], %1;" :: "r"(a), "l"(v) : "memory")

DEVINL void ldsm_x4(uint32_t* r, uint32_t addr) {
    asm volatile("ldmatrix.sync.aligned.m8n8.x4.shared.b16 {%0,%1,%2,%3}, [%4];"
                 : "=r"(r[0]), "=r"(r[1]), "=r"(r[2]), "=r"(r[3]) : "r"(addr));
}

DEVINL void mma16816(float* c, const uint32_t* a, uint32_t b0, uint32_t b1) {
    asm volatile(
        "mma.sync.aligned.m16n8k16.row.col.f32.bf16.bf16.f32 "
        "{%0,%1,%2,%3}, {%4,%5,%6,%7}, {%8,%9}, {%0,%1,%2,%3};"
        : "+f"(c[0]), "+f"(c[1]), "+f"(c[2]), "+f"(c[3])
        : "r"(a[0]), "r"(a[1]), "r"(a[2]), "r"(a[3]), "r"(b0), "r"(b1));
}

DEVINL uint32_t pack_bf16(float lo, float hi) {   // low half = lo, high = hi
    uint32_t r;
    asm("cvt.rn.bf16x2.f32 %0, %1, %2;" : "=r"(r) : "f"(hi), "f"(lo));
    return r;
}
DEVINL float bf16_rt(float a) { return __bfloat162float(__float2bfloat16(a)); }
DEVINL uint64_t pack2(uint32_t lo, uint32_t hi) { return (uint64_t)lo | ((uint64_t)hi << 32); }

// accurate 2-way softmax from logit diff (no 1-p cancellation)
DEVINL void sig2(float t, float& p0, float& p1) {
    t = fminf(fmaxf(t, -60.f), 60.f);
    float e   = __expf(-t);
    float inv = __fdividef(1.f, 1.f + e);
    p1 = inv;
    p0 = e * inv;
}

// SMEM: bias [0,512); stages @1024, each: Ahi(36864) Alo(36864) Whi(18432) Wlo(18432)
static constexpr uint32_t OFF_BIAS  = 0;
static constexpr uint32_t OFF_STAGE = 1024;
static constexpr uint32_t SO_AHI = 0;
static constexpr uint32_t SO_ALO = 36864;
static constexpr uint32_t SO_WHI = 73728;
static constexpr uint32_t SO_WLO = 92160;
static constexpr uint32_t STAGE_BYTES = 110592;
static constexpr uint32_t GEMM_SMEM = OFF_STAGE + 2 * STAGE_BYTES;  // 222208

extern __shared__ char dyn_smem[];

__global__ void __launch_bounds__(256, 1)
hsm_gemm(const float* __restrict__ x, const float* __restrict__ W,
         const float* __restrict__ bias) {
    const uint32_t sb = smem_u32(dyn_smem);
    const int tid = threadIdx.x, wid = tid >> 5, lid = tid & 31;
    const int n0 = blockIdx.x * TILE_N;
    const int mw = wid & 3;   // M warp tile (4 x 64 = 256)
    const int nw = wid >> 2;  // N warp tile (2 x 64 = 128)

    float* sBias = (float*)(dyn_smem + OFF_BIAS);
    if (tid < 128) {
        const int n = n0 + tid;
        sBias[tid] = (n < NNODES) ? (__ldg(bias + 2 * n + 1) - __ldg(bias + 2 * n)) : 0.f;
    }

    // fp32 accumulators: 4 m16 tiles x 8 n8 tiles x 4 regs
    float acc[4][8][4];
    #pragma unroll
    for (int i = 0; i < 4; i++)
        #pragma unroll
        for (int j = 0; j < 8; j++)
            #pragma unroll
            for (int k = 0; k < 4; k++) acc[i][j][k] = 0.f;

    // ---- copy one K chunk into stage (c&1): batched LDG (MLP=16/half),
    //      then f32 -> diff -> bf16 hi/lo converts + STS ----
    auto copy_chunk = [&](int c) {
        const uint32_t st = sb + OFF_STAGE + (uint32_t)(c & 1) * STAGE_BYTES;
        const int k0 = c * KC;
        // W: batch all 16 row loads first (independent -> overlapped in LSU)
        float4 wq[16];
        #pragma unroll
        for (int it = 0; it < 16; ++it) {
            const int node = n0 + wid * 16 + it;
            wq[it] = (node < NNODES)
                ? __ldg((const float4*)(W + (size_t)node * 1024 + k0 * 2) + lid)
                : make_float4(0.f, 0.f, 0.f, 0.f);
        }
        #pragma unroll
        for (int it = 0; it < 16; ++it) {
            const int row = wid * 16 + it;
            const float d0 = wq[it].y - wq[it].x;   // e = k0 + 2*lid
            const float d1 = wq[it].w - wq[it].z;   // e + 1
            const uint32_t hv = pack_bf16(d0, d1);
            const uint32_t lv = pack_bf16(d0 - bf16_rt(d0), d1 - bf16_rt(d1));
            const uint32_t off = (uint32_t)(row * SROW + 2 * lid) * 2;
            STS32(st + SO_WHI + off, hv);
            STS32(st + SO_WLO + off, lv);
        }
        // A (x): batch 16 loads, then convert+store
        float4 aq[16];
        #pragma unroll
        for (int it = 0; it < 16; ++it) {
            const int idx = it * 256 + tid;
            aq[it] = __ldg((const float4*)(x + (size_t)(idx >> 4) * EDIM + k0) + (idx & 15));
        }
        #pragma unroll
        for (int it = 0; it < 16; ++it) {
            const int idx = it * 256 + tid;
            const int row = idx >> 4, f = idx & 15;
            const float4 q = aq[it];
            const uint32_t h01 = pack_bf16(q.x, q.y);
            const uint32_t h23 = pack_bf16(q.z, q.w);
            const uint32_t l01 = pack_bf16(q.x - bf16_rt(q.x), q.y - bf16_rt(q.y));
            const uint32_t l23 = pack_bf16(q.z - bf16_rt(q.z), q.w - bf16_rt(q.w));
            const uint32_t off = (uint32_t)(row * (SROW * 2) + f * 8);
            STS64(st + SO_AHI + off, pack2(h01, h23));
            STS64(st + SO_ALO + off, pack2(l01, l23));
        }
    };

    // ---- MMA one chunk: 4 k16-steps x 3 hi/lo passes x (4x8 tile grid) ----
    auto mma_chunk = [&](int c) {
        const uint32_t st = sb + OFF_STAGE + (uint32_t)(c & 1) * STAGE_BYTES;
        const int arow = mw * 64 + (lid & 15);            // A ldmatrix row
        const int brow = nw * 64 + (lid & 7) + ((lid & 16) ? 8 : 0);
        #pragma unroll
        for (int ks = 0; ks < 4; ks++) {
            const int kA = ks * 16 + ((lid & 16) ? 8 : 0);
            const int kB = ks * 16 + ((lid & 8) ? 8 : 0);
            #pragma unroll
            for (int pass = 0; pass < 3; pass++) {
                const uint32_t Ab = st + (pass == 2 ? SO_ALO : SO_AHI);
                const uint32_t Bb = st + (pass == 1 ? SO_WLO : SO_WHI);
                uint32_t af[4][4], bf[4][4];
                #pragma unroll
                for (int mt = 0; mt < 4; mt++)
                    ldsm_x4(af[mt], Ab + (uint32_t)((arow + mt * 16) * SROW + kA) * 2);
                #pragma unroll
                for (int j = 0; j < 4; j++)
                    ldsm_x4(bf[j], Bb + (uint32_t)((brow + j * 16) * SROW + kB) * 2);
                #pragma unroll
                for (int mt = 0; mt < 4; mt++)
                    #pragma unroll
                    for (int j = 0; j < 4; j++) {
                        mma16816(acc[mt][2 * j],     af[mt], bf[j][0], bf[j][1]);
                        mma16816(acc[mt][2 * j + 1], af[mt], bf[j][2], bf[j][3]);
                    }
            }
        }
    };

    copy_chunk(0);
    __syncthreads();
    for (int c = 0; c < NCHUNK; c++) {
        if (c + 1 < NCHUNK) copy_chunk(c + 1);   // writes other stage
        mma_chunk(c);
        __syncthreads();
    }

    // ---- epilogue: + bias diff, store delta (32B sectors fully used) ----
    #pragma unroll
    for (int mt = 0; mt < 4; mt++) {
        const int r0 = mw * 64 + mt * 16 + (lid >> 2);
        #pragma unroll
        for (int nt = 0; nt < 8; nt++) {
            const int cl = nw * 64 + nt * 8 + 2 * (lid & 3);
            const float b0 = sBias[cl], b1 = sBias[cl + 1];
            float2* p0 = (float2*)(g_delta + (size_t)r0 * NPAD + n0 + cl);
            float2* p1 = (float2*)(g_delta + (size_t)(r0 + 8) * NPAD + n0 + cl);
            *p0 = make_float2(acc[mt][nt][0] + b0, acc[mt][nt][1] + b1);
            *p1 = make_float2(acc[mt][nt][2] + b0, acc[mt][nt][3] + b1);
        }
    }
}

// Tree kernel v2: grid (8 chunks, 256 batch), 256 threads, tiny smem.
// Each block owns a depth-3 subtree (2048 leaves). Factor at depth d is
// determined by the depth-(d+1) ancestor label a = leaf >> (13-d):
//   node = (a>>1)-1, bit = a&1.
__global__ void __launch_bounds__(256, 8)
hsm_tree(float* __restrict__ out) {
    __shared__ float cumA[128], cumB[128];
    const int chunk = blockIdx.x;           // 0..7
    const int b     = blockIdx.y;           // 0..255
    const int tid   = threadIdx.x;
    const float* dr = g_delta + (size_t)b * NPAD;

    // prefix product for depths 0..2 (constant over the chunk)
    if (tid == 0) {
        const int A3 = 8 + chunk;           // depth-3 ancestor label
        float P = 1.f;
        #pragma unroll
        for (int d = 0; d < 3; d++) {
            const int anc = A3 >> (2 - d);  // depth-(d+1) ancestor label
            float p0, p1;
            sig2(dr[(anc >> 1) - 1], p0, p1);
            P *= (anc & 1) ? p1 : p0;
        }
        cumA[0] = P;
    }
    __syncthreads();

    // subtree levels: depths 3..9 -> cum over 128 depth-10 prefixes
    float* cur = cumA;
    float* nxt = cumB;
    #pragma unroll
    for (int s = 1; s <= 7; s++) {
        if (tid < (1 << s)) {
            const int anc = ((8 + chunk) << s) + tid;   // depth-(3+s) label
            float p0, p1;
            sig2(dr[(anc >> 1) - 1], p0, p1);
            nxt[tid] = cur[tid >> 1] * ((anc & 1) ? p1 : p0);
        }
        __syncthreads();
        float* t = cur; cur = nxt; nxt = t;
    }

    // leaves: 1024 pairs per chunk; 4 pairs per thread; depths 10..13
    float2* out2 = (float2*)(out + (size_t)b * VLEAF);
    #pragma unroll
    for (int it = 0; it < 4; it++) {
        const int t  = it * 256 + tid;
        const int jp = chunk * 1024 + t;    // global pair index
        float c = cur[t >> 3];
        float q0, q1;
        sig2(dr[(jp >> 3) + 1023], q0, q1); c *= ((jp >> 2) & 1) ? q1 : q0;  // d=10
        sig2(dr[(jp >> 2) + 2047], q0, q1); c *= ((jp >> 1) & 1) ? q1 : q0;  // d=11
        sig2(dr[(jp >> 1) + 4095], q0, q1); c *= (jp & 1) ? q1 : q0;         // d=12
        sig2(dr[jp + 8191], q0, q1);                                          // d=13
        out2[jp] = make_float2(c * q0, c * q1);
    }
}

extern "C" void kernel_launch(void* const* d_in, const int* in_sizes, int n_in,
                              void* d_out, int out_size) {
    (void)in_sizes; (void)n_in; (void)out_size;
    const float* x    = (const float*)d_in[0];
    const float* W    = (const float*)d_in[1];
    const float* bias = (const float*)d_in[2];
    float* out = (float*)d_out;

    cudaFuncSetAttribute(hsm_gemm, cudaFuncAttributeMaxDynamicSharedMemorySize, GEMM_SMEM);

    hsm_gemm<<<NTILES, 256, GEMM_SMEM>>>(x, W, bias);
    dim3 tgrid(8, 256);
    hsm_tree<<<tgrid, 256>>>(out);
}